// round 11
// baseline (speedup 1.0000x reference)
#include <cuda_runtime.h>
#include <cstddef>
#include <cstdint>

// ---------------------------------------------------------------------------
// HMP hierarchical message passing — R11: tensor-core MLPs, 256-thr blocks.
//  * 8 warps/block, 1 m16-tile (16 rows) per warp, 128-row tile per block
//    -> same SMEM (~107KB), 2 blocks/SM, 16 warps/SM (2x R10 occupancy)
//  * weights pre-split (tf32 hi/lo) in SMEM; 3-term tf32 mma (~fp32 accuracy)
//  * x tile staged cooperatively (coalesced gather), conflict-free layouts
// ---------------------------------------------------------------------------

typedef unsigned int uint32;

#define N1MAX 250000
#define N2MAX 500000
#define N3MAX 1000000

__device__ float g_h2   [(size_t)N2MAX * 32];
__device__ float g_h3   [(size_t)N3MAX * 32];
__device__ float g_acc3 [(size_t)N3MAX * 32];
__device__ float g_acc2 [(size_t)N2MAX * 32];
__device__ float g_acc1 [(size_t)N1MAX * 32];
__device__ float g_accr [(size_t)N1MAX * 32];
__device__ float g_h1mid[(size_t)N1MAX * 32];

// ---------------------------------------------------------------------------
__device__ __forceinline__ float tanh_fast(float x)
{
    float cx = fminf(fmaxf(x, -15.f), 15.f);
    float e  = __expf(2.f * cx);
    return __fdividef(e - 1.f, e + 1.f);
}

__device__ __forceinline__ uint32 f2tf32(float f)
{
    uint32 r;
    asm("cvt.rna.tf32.f32 %0, %1;" : "=r"(r) : "f"(f));
    return r;
}
__device__ __forceinline__ void split_tf32(float v, uint32& hi, uint32& lo)
{
    hi = f2tf32(v);
    lo = f2tf32(v - __uint_as_float(hi));
}

__device__ __forceinline__ void mma8(float c[4],
    uint32 a0, uint32 a1, uint32 a2, uint32 a3, uint32 b0, uint32 b1)
{
    asm volatile(
        "mma.sync.aligned.m16n8k8.row.col.f32.tf32.tf32.f32 "
        "{%0,%1,%2,%3},{%4,%5,%6,%7},{%8,%9},{%0,%1,%2,%3};"
        : "+f"(c[0]), "+f"(c[1]), "+f"(c[2]), "+f"(c[3])
        : "r"(a0), "r"(a1), "r"(a2), "r"(a3), "r"(b0), "r"(b1));
}

// ---------------------------------------------------------------------------
__global__ void __launch_bounds__(256) zero_multi_kernel(
    float4* __restrict__ p0, int n0, float4* __restrict__ p1, int n1,
    float4* __restrict__ p2, int n2, float4* __restrict__ p3, int n3,
    float4* __restrict__ p4, int n4)
{
    const float4 z = make_float4(0.f, 0.f, 0.f, 0.f);
    int total = n0 + n1 + n2 + n3 + n4;
    for (int i = blockIdx.x * 256 + threadIdx.x; i < total; i += gridDim.x * 256) {
        int j = i;
        if (j < n0) { p0[j] = z; continue; } j -= n0;
        if (j < n1) { p1[j] = z; continue; } j -= n1;
        if (j < n2) { p2[j] = z; continue; } j -= n2;
        if (j < n3) { p3[j] = z; continue; } j -= n3;
        p4[j] = z;
    }
}

// ---------------------------------------------------------------------------
// Tensor-core MLP: 128-row tile / block, 8 warps, 1 m16-tile per warp.
// x = [ self[r] | blocks from 'other' ], P blocks of 32 (P=2 or 3).
// out[r] = tanh(x@W1+b1)@W2+b2
template<int P, bool GATHER>
__global__ void __launch_bounds__(256) mlp_mma_kernel(
    const float* __restrict__ self, const float* __restrict__ other,
    const int* __restrict__ gi0, const int* __restrict__ gi1,
    const float* __restrict__ W1, const float* __restrict__ b1,
    const float* __restrict__ W2, const float* __restrict__ b2,
    float* __restrict__ out, int n)
{
    extern __shared__ float sm[];
    const int K1 = P * 32;
    const int XS = K1 + 4;                         // conflict-free: 4g+t4
    float*  xs   = sm;                             // [128][XS]
    uint32* w1hi = (uint32*)(xs + 128 * XS);       // [K1][36]
    uint32* w1lo = w1hi + K1 * 36;
    uint32* w2hi = w1lo + K1 * 36;                 // [32][36]
    uint32* w2lo = w2hi + 32 * 36;
    float*  hs   = (float*)(w2lo + 32 * 36);       // [128][36]
    float*  b1s  = hs + 128 * 36;                  // [32]
    float*  b2s  = b1s + 32;                       // [32]

    int tid  = threadIdx.x;
    int tile = blockIdx.x * 128;

    // ---- weights: load + pre-split into hi/lo ----
    for (int i = tid; i < K1 * 32; i += 256) {
        uint32 hi, lo;
        split_tf32(W1[i], hi, lo);
        int idx = (i >> 5) * 36 + (i & 31);
        w1hi[idx] = hi; w1lo[idx] = lo;
    }
    for (int i = tid; i < 32 * 32; i += 256) {
        uint32 hi, lo;
        split_tf32(W2[i], hi, lo);
        int idx = (i >> 5) * 36 + (i & 31);
        w2hi[idx] = hi; w2lo[idx] = lo;
    }
    if (tid < 32) { b1s[tid] = b1[tid]; b2s[tid] = b2[tid]; }

    // ---- stage x tile: 8 lanes per row (coalesced, incl. gathers) ----
    {
        int rl = tid >> 3;       // 0..31
        int c  = tid & 7;
        for (int pass = 0; pass < 4; pass++) {
            int row = rl + pass * 32;
            int r = min(tile + row, n - 1);
#pragma unroll
            for (int p = 0; p < P; p++) {
                const float* src;
                if (p == 0)      src = self + (size_t)r * 32;
                else if (GATHER) src = other + (size_t)((p == 1) ? gi0[r] : gi1[r]) * 32;
                else             src = other + (size_t)r * 32;
                float4 v = ((const float4*)src)[c];
                *(float4*)(xs + row * XS + p * 32 + c * 4) = v;
            }
        }
    }
    __syncthreads();

    int lane = tid & 31;
    int warp = tid >> 5;       // 0..7
    int g    = lane >> 2;      // groupID
    int t4   = lane & 3;       // threadID_in_group
    int rowb = warp * 16;      // this warp's 16 rows

    // ---------------- layer 1 ----------------
    float c1f[4][4];
#pragma unroll
    for (int nt = 0; nt < 4; nt++) {
        int col0 = nt * 8 + 2 * t4;
        c1f[nt][0] = b1s[col0];  c1f[nt][1] = b1s[col0 + 1];
        c1f[nt][2] = c1f[nt][0]; c1f[nt][3] = c1f[nt][1];
    }
    {
        const float* xr0 = xs + (rowb + g) * XS;
        const float* xr1 = xs + (rowb + 8 + g) * XS;
#pragma unroll 2
        for (int kt = 0; kt < P * 4; kt++) {
            int k0 = kt * 8 + t4;
            uint32 ah[4], al[4];
            split_tf32(xr0[k0],     ah[0], al[0]);
            split_tf32(xr1[k0],     ah[1], al[1]);
            split_tf32(xr0[k0 + 4], ah[2], al[2]);
            split_tf32(xr1[k0 + 4], ah[3], al[3]);
            int wk0 = (kt * 8 + t4) * 36;
            int wk1 = (kt * 8 + t4 + 4) * 36;
#pragma unroll
            for (int nt = 0; nt < 4; nt++) {
                int nc = nt * 8 + g;
                uint32 bh0 = w1hi[wk0 + nc], bh1 = w1hi[wk1 + nc];
                uint32 bl0 = w1lo[wk0 + nc], bl1 = w1lo[wk1 + nc];
                mma8(c1f[nt], ah[0], ah[1], ah[2], ah[3], bh0, bh1);
                mma8(c1f[nt], ah[0], ah[1], ah[2], ah[3], bl0, bl1);
                mma8(c1f[nt], al[0], al[1], al[2], al[3], bh0, bh1);
            }
        }
    }

    // tanh + stage h (own warp rows only)
#pragma unroll
    for (int nt = 0; nt < 4; nt++) {
        int col0 = nt * 8 + 2 * t4;
        *(float2*)(hs + (rowb + g) * 36 + col0) =
            make_float2(tanh_fast(c1f[nt][0]), tanh_fast(c1f[nt][1]));
        *(float2*)(hs + (rowb + 8 + g) * 36 + col0) =
            make_float2(tanh_fast(c1f[nt][2]), tanh_fast(c1f[nt][3]));
    }
    __syncwarp();

    // ---------------- layer 2 ----------------
    float d[4][4];
#pragma unroll
    for (int nt = 0; nt < 4; nt++) {
        int col0 = nt * 8 + 2 * t4;
        d[nt][0] = b2s[col0];  d[nt][1] = b2s[col0 + 1];
        d[nt][2] = d[nt][0];   d[nt][3] = d[nt][1];
    }
    {
        const float* hr0 = hs + (rowb + g) * 36;
        const float* hr1 = hs + (rowb + 8 + g) * 36;
#pragma unroll
        for (int kt = 0; kt < 4; kt++) {
            int k0 = kt * 8 + t4;
            uint32 ah[4], al[4];
            split_tf32(hr0[k0],     ah[0], al[0]);
            split_tf32(hr1[k0],     ah[1], al[1]);
            split_tf32(hr0[k0 + 4], ah[2], al[2]);
            split_tf32(hr1[k0 + 4], ah[3], al[3]);
            int wk0 = (kt * 8 + t4) * 36;
            int wk1 = (kt * 8 + t4 + 4) * 36;
#pragma unroll
            for (int nt = 0; nt < 4; nt++) {
                int nc = nt * 8 + g;
                uint32 bh0 = w2hi[wk0 + nc], bh1 = w2hi[wk1 + nc];
                uint32 bl0 = w2lo[wk0 + nc], bl1 = w2lo[wk1 + nc];
                mma8(d[nt], ah[0], ah[1], ah[2], ah[3], bh0, bh1);
                mma8(d[nt], ah[0], ah[1], ah[2], ah[3], bl0, bl1);
                mma8(d[nt], al[0], al[1], al[2], al[3], bh0, bh1);
            }
        }
    }

    // ---- store ----
    {
        int r0g = tile + rowb + g;
        int r1g = r0g + 8;
#pragma unroll
        for (int nt = 0; nt < 4; nt++) {
            int col0 = nt * 8 + 2 * t4;
            if (r0g < n)
                *(float2*)(out + (size_t)r0g * 32 + col0) =
                    make_float2(d[nt][0], d[nt][1]);
            if (r1g < n)
                *(float2*)(out + (size_t)r1g * 32 + col0) =
                    make_float2(d[nt][2], d[nt][3]);
        }
    }
}

// ---------------------------------------------------------------------------
// acc[i0[r]] += src[r]; acc[i1[r]] += src[r]   (row-wise float4 atomics)
__global__ void __launch_bounds__(256) scatter2_kernel(
    const float* __restrict__ src,
    const int* __restrict__ i0, const int* __restrict__ i1,
    float* __restrict__ acc, int n)
{
    int r = blockIdx.x * 256 + threadIdx.x;
    if (r >= n) return;
    const float4* s = (const float4*)(src + (size_t)r * 32);
    float4* d0 = (float4*)(acc + (size_t)i0[r] * 32);
    float4* d1 = (float4*)(acc + (size_t)i1[r] * 32);
#pragma unroll
    for (int q = 0; q < 8; q++) {
        float4 v = s[q];
        atomicAdd(d0 + q, v);
        atomicAdd(d1 + q, v);
    }
}

// acc[dstidx[r]] += src[srcidx[r]]
__global__ void __launch_bounds__(256) scatter1_kernel(
    const float* __restrict__ src,
    const int* __restrict__ srcidx, const int* __restrict__ dstidx,
    float* __restrict__ acc, int n)
{
    int r = blockIdx.x * 256 + threadIdx.x;
    if (r >= n) return;
    const float4* s = (const float4*)(src + (size_t)srcidx[r] * 32);
    float4* d = (float4*)(acc + (size_t)dstidx[r] * 32);
#pragma unroll
    for (int q = 0; q < 8; q++) atomicAdd(d + q, s[q]);
}

// ---------------------------------------------------------------------------
static inline int nblk256(int n)  { return (n + 255) / 256; }
static inline int nblk128t(int n) { return (n + 127) / 128; }

static inline int smem_bytes(int P)
{
    int K1 = P * 32;
    int floats = 128 * (K1 + 4)        // xs
               + 2 * K1 * 36           // w1 hi/lo
               + 2 * 32 * 36           // w2 hi/lo
               + 128 * 36              // hs
               + 64;                   // biases
    return floats * 4;
}

extern "C" void kernel_launch(void* const* d_in, const int* in_sizes, int n_in,
                              void* d_out, int out_size)
{
    const float* h1     = (const float*)d_in[0];
    const float* h2     = (const float*)d_in[1];
    const float* h3     = (const float*)d_in[2];
    const float* h4     = (const float*)d_in[3];
    const float* upW1   = (const float*)d_in[4];
    const float* upb1   = (const float*)d_in[5];
    const float* upW2   = (const float*)d_in[6];
    const float* upb2   = (const float*)d_in[7];
    const float* dnW1   = (const float*)d_in[8];
    const float* dnb1   = (const float*)d_in[9];
    const float* dnW2   = (const float*)d_in[10];
    const float* dnb2   = (const float*)d_in[11];
    const float* rW1    = (const float*)d_in[12];
    const float* rb1    = (const float*)d_in[13];
    const float* rW2    = (const float*)d_in[14];
    const float* rb2    = (const float*)d_in[15];
    const int* idx2_0   = (const int*)d_in[16];
    const int* idx2_1   = (const int*)d_in[17];
    const int* idx3_0   = (const int*)d_in[18];
    const int* idx3_1   = (const int*)d_in[19];
    const int* idx4_0   = (const int*)d_in[20];
    const int* idx4_1   = (const int*)d_in[21];
    const int* ring_src = (const int*)d_in[22];
    const int* ring_dst = (const int*)d_in[23];

    const int N1 = in_sizes[0] / 32;
    const int N2 = in_sizes[1] / 32;
    const int N3 = in_sizes[2] / 32;
    const int N4 = in_sizes[3] / 32;
    const int ER = in_sizes[22];
    const int NR = out_size / 32 - (N1 + N2 + N3 + N4);

    float* out  = (float*)d_out;
    float* out1 = out;
    float* out2 = out1 + (size_t)N1 * 32;
    float* out3 = out2 + (size_t)N2 * 32;
    float* out4 = out3 + (size_t)N3 * 32;
    float* outR = out4 + (size_t)N4 * 32;

    float *h2buf, *h3buf, *acc3, *acc2, *acc1, *accr, *h1mid;
    cudaGetSymbolAddress((void**)&h2buf, g_h2);
    cudaGetSymbolAddress((void**)&h3buf, g_h3);
    cudaGetSymbolAddress((void**)&acc3,  g_acc3);
    cudaGetSymbolAddress((void**)&acc2,  g_acc2);
    cudaGetSymbolAddress((void**)&acc1,  g_acc1);
    cudaGetSymbolAddress((void**)&accr,  g_accr);
    cudaGetSymbolAddress((void**)&h1mid, g_h1mid);

    const int SM3 = smem_bytes(3);
    const int SM2 = smem_bytes(2);
    cudaFuncSetAttribute(mlp_mma_kernel<3, true>,
        cudaFuncAttributeMaxDynamicSharedMemorySize, SM3);
    cudaFuncSetAttribute(mlp_mma_kernel<2, false>,
        cudaFuncAttributeMaxDynamicSharedMemorySize, SM2);

    // ---- zero all accumulators once ----
    zero_multi_kernel<<<2048, 256>>>(
        (float4*)acc3, N3 * 8, (float4*)acc2, N2 * 8,
        (float4*)acc1, N1 * 8, (float4*)accr, N1 * 8,
        (float4*)outR, NR * 8);

    // ---- up pass ----
    mlp_mma_kernel<3, true><<<nblk128t(N2), 256, SM3>>>(h2, h1, idx2_0, idx2_1,
        upW1 + 0 * 96 * 32, upb1 + 0 * 32, upW2 + 0 * 1024, upb2 + 0 * 32,
        h2buf, N2);
    mlp_mma_kernel<3, true><<<nblk128t(N3), 256, SM3>>>(h3, h2buf, idx3_0, idx3_1,
        upW1 + 1 * 96 * 32, upb1 + 1 * 32, upW2 + 1 * 1024, upb2 + 1 * 32,
        h3buf, N3);
    mlp_mma_kernel<3, true><<<nblk128t(N4), 256, SM3>>>(h4, h3buf, idx4_0, idx4_1,
        upW1 + 2 * 96 * 32, upb1 + 2 * 32, upW2 + 2 * 1024, upb2 + 2 * 32,
        out4, N4);

    // ---- down pass ----
    scatter2_kernel<<<nblk256(N4), 256>>>(out4, idx4_0, idx4_1, acc3, N4);
    mlp_mma_kernel<2, false><<<nblk128t(N3), 256, SM2>>>(h3buf, acc3, 0, 0,
        dnW1 + 2 * 64 * 32, dnb1 + 2 * 32, dnW2 + 2 * 1024, dnb2 + 2 * 32,
        out3, N3);

    scatter2_kernel<<<nblk256(N3), 256>>>(out3, idx3_0, idx3_1, acc2, N3);
    mlp_mma_kernel<2, false><<<nblk128t(N2), 256, SM2>>>(h2buf, acc2, 0, 0,
        dnW1 + 1 * 64 * 32, dnb1 + 1 * 32, dnW2 + 1 * 1024, dnb2 + 1 * 32,
        out2, N2);

    scatter2_kernel<<<nblk256(N2), 256>>>(out2, idx2_0, idx2_1, acc1, N2);
    mlp_mma_kernel<2, false><<<nblk128t(N1), 256, SM2>>>(h1, acc1, 0, 0,
        dnW1 + 0 * 64 * 32, dnb1 + 0 * 32, dnW2 + 0 * 1024, dnb2 + 0 * 32,
        h1mid, N1);

    // ---- ring ----
    scatter1_kernel<<<nblk256(ER), 256>>>(h1mid, ring_src, ring_dst, outR, ER);
    scatter1_kernel<<<nblk256(ER), 256>>>(outR, ring_dst, ring_src, accr, ER);
    mlp_mma_kernel<2, false><<<nblk128t(N1), 256, SM2>>>(h1mid, accr, 0, 0,
        rW1, rb1, rW2, rb2, out1, N1);
}

// round 12
// speedup vs baseline: 1.0207x; 1.0207x over previous
#include <cuda_runtime.h>
#include <cstddef>
#include <cstdint>

// ---------------------------------------------------------------------------
// HMP hierarchical message passing — R12: tensor-core MLPs, term-split accs.
//  * each tf32 split term (hh, hl, lh) gets its OWN mma accumulator
//    -> 12 independent mma chains per warp (vs 4), 3x shorter critical path
//  * 256-thr blocks, 8 warps, 1 m16-tile per warp, 128-row tile per block
//  * weights pre-split (tf32 hi/lo) in SMEM; coalesced gather staging
// ---------------------------------------------------------------------------

typedef unsigned int uint32;

#define N1MAX 250000
#define N2MAX 500000
#define N3MAX 1000000

__device__ float g_h2   [(size_t)N2MAX * 32];
__device__ float g_h3   [(size_t)N3MAX * 32];
__device__ float g_acc3 [(size_t)N3MAX * 32];
__device__ float g_acc2 [(size_t)N2MAX * 32];
__device__ float g_acc1 [(size_t)N1MAX * 32];
__device__ float g_accr [(size_t)N1MAX * 32];
__device__ float g_h1mid[(size_t)N1MAX * 32];

// ---------------------------------------------------------------------------
__device__ __forceinline__ float tanh_fast(float x)
{
    float cx = fminf(fmaxf(x, -15.f), 15.f);
    float e  = __expf(2.f * cx);
    return __fdividef(e - 1.f, e + 1.f);
}

__device__ __forceinline__ uint32 f2tf32(float f)
{
    uint32 r;
    asm("cvt.rna.tf32.f32 %0, %1;" : "=r"(r) : "f"(f));
    return r;
}
__device__ __forceinline__ void split_tf32(float v, uint32& hi, uint32& lo)
{
    hi = f2tf32(v);
    lo = f2tf32(v - __uint_as_float(hi));
}

__device__ __forceinline__ void mma8(float c[4],
    uint32 a0, uint32 a1, uint32 a2, uint32 a3, uint32 b0, uint32 b1)
{
    asm volatile(
        "mma.sync.aligned.m16n8k8.row.col.f32.tf32.tf32.f32 "
        "{%0,%1,%2,%3},{%4,%5,%6,%7},{%8,%9},{%0,%1,%2,%3};"
        : "+f"(c[0]), "+f"(c[1]), "+f"(c[2]), "+f"(c[3])
        : "r"(a0), "r"(a1), "r"(a2), "r"(a3), "r"(b0), "r"(b1));
}

// ---------------------------------------------------------------------------
__global__ void __launch_bounds__(256) zero_multi_kernel(
    float4* __restrict__ p0, int n0, float4* __restrict__ p1, int n1,
    float4* __restrict__ p2, int n2, float4* __restrict__ p3, int n3,
    float4* __restrict__ p4, int n4)
{
    const float4 z = make_float4(0.f, 0.f, 0.f, 0.f);
    int total = n0 + n1 + n2 + n3 + n4;
    for (int i = blockIdx.x * 256 + threadIdx.x; i < total; i += gridDim.x * 256) {
        int j = i;
        if (j < n0) { p0[j] = z; continue; } j -= n0;
        if (j < n1) { p1[j] = z; continue; } j -= n1;
        if (j < n2) { p2[j] = z; continue; } j -= n2;
        if (j < n3) { p3[j] = z; continue; } j -= n3;
        p4[j] = z;
    }
}

// ---------------------------------------------------------------------------
// Tensor-core MLP: 128-row tile / block, 8 warps, 1 m16-tile per warp.
// Split terms accumulate into separate fragments (12 independent chains).
template<int P, bool GATHER>
__global__ void __launch_bounds__(256) mlp_mma_kernel(
    const float* __restrict__ self, const float* __restrict__ other,
    const int* __restrict__ gi0, const int* __restrict__ gi1,
    const float* __restrict__ W1, const float* __restrict__ b1,
    const float* __restrict__ W2, const float* __restrict__ b2,
    float* __restrict__ out, int n)
{
    extern __shared__ float sm[];
    const int K1 = P * 32;
    const int XS = K1 + 4;
    float*  xs   = sm;                             // [128][XS]
    uint32* w1hi = (uint32*)(xs + 128 * XS);       // [K1][36]
    uint32* w1lo = w1hi + K1 * 36;
    uint32* w2hi = w1lo + K1 * 36;                 // [32][36]
    uint32* w2lo = w2hi + 32 * 36;
    float*  hs   = (float*)(w2lo + 32 * 36);       // [128][36]
    float*  b1s  = hs + 128 * 36;                  // [32]
    float*  b2s  = b1s + 32;                       // [32]

    int tid  = threadIdx.x;
    int tile = blockIdx.x * 128;

    // ---- weights: load + pre-split into hi/lo ----
    for (int i = tid; i < K1 * 32; i += 256) {
        uint32 hi, lo;
        split_tf32(W1[i], hi, lo);
        int idx = (i >> 5) * 36 + (i & 31);
        w1hi[idx] = hi; w1lo[idx] = lo;
    }
    for (int i = tid; i < 32 * 32; i += 256) {
        uint32 hi, lo;
        split_tf32(W2[i], hi, lo);
        int idx = (i >> 5) * 36 + (i & 31);
        w2hi[idx] = hi; w2lo[idx] = lo;
    }
    if (tid < 32) { b1s[tid] = b1[tid]; b2s[tid] = b2[tid]; }

    // ---- stage x tile (coalesced, incl. gathers) ----
    {
        int rl = tid >> 3;
        int c  = tid & 7;
        for (int pass = 0; pass < 4; pass++) {
            int row = rl + pass * 32;
            int r = min(tile + row, n - 1);
#pragma unroll
            for (int p = 0; p < P; p++) {
                const float* src;
                if (p == 0)      src = self + (size_t)r * 32;
                else if (GATHER) src = other + (size_t)((p == 1) ? gi0[r] : gi1[r]) * 32;
                else             src = other + (size_t)r * 32;
                float4 v = ((const float4*)src)[c];
                *(float4*)(xs + row * XS + p * 32 + c * 4) = v;
            }
        }
    }
    __syncthreads();

    int lane = tid & 31;
    int warp = tid >> 5;
    int g    = lane >> 2;
    int t4   = lane & 3;
    int rowb = warp * 16;

    // ---------------- layer 1: 3 term accumulators ----------------
    float chh[4][4], chl[4][4], clh[4][4];
#pragma unroll
    for (int nt = 0; nt < 4; nt++) {
        int col0 = nt * 8 + 2 * t4;
        chh[nt][0] = b1s[col0];  chh[nt][1] = b1s[col0 + 1];
        chh[nt][2] = chh[nt][0]; chh[nt][3] = chh[nt][1];
#pragma unroll
        for (int q = 0; q < 4; q++) { chl[nt][q] = 0.f; clh[nt][q] = 0.f; }
    }
    {
        const float* xr0 = xs + (rowb + g) * XS;
        const float* xr1 = xs + (rowb + 8 + g) * XS;
#pragma unroll 2
        for (int kt = 0; kt < P * 4; kt++) {
            int k0 = kt * 8 + t4;
            uint32 ah[4], al[4];
            split_tf32(xr0[k0],     ah[0], al[0]);
            split_tf32(xr1[k0],     ah[1], al[1]);
            split_tf32(xr0[k0 + 4], ah[2], al[2]);
            split_tf32(xr1[k0 + 4], ah[3], al[3]);
            int wk0 = (kt * 8 + t4) * 36;
            int wk1 = (kt * 8 + t4 + 4) * 36;
#pragma unroll
            for (int nt = 0; nt < 4; nt++) {
                int nc = nt * 8 + g;
                uint32 bh0 = w1hi[wk0 + nc], bh1 = w1hi[wk1 + nc];
                uint32 bl0 = w1lo[wk0 + nc], bl1 = w1lo[wk1 + nc];
                mma8(chh[nt], ah[0], ah[1], ah[2], ah[3], bh0, bh1);
                mma8(chl[nt], ah[0], ah[1], ah[2], ah[3], bl0, bl1);
                mma8(clh[nt], al[0], al[1], al[2], al[3], bh0, bh1);
            }
        }
    }

    // combine terms + tanh + stage h
#pragma unroll
    for (int nt = 0; nt < 4; nt++) {
        int col0 = nt * 8 + 2 * t4;
        float v0 = chh[nt][0] + (chl[nt][0] + clh[nt][0]);
        float v1 = chh[nt][1] + (chl[nt][1] + clh[nt][1]);
        float v2 = chh[nt][2] + (chl[nt][2] + clh[nt][2]);
        float v3 = chh[nt][3] + (chl[nt][3] + clh[nt][3]);
        *(float2*)(hs + (rowb + g) * 36 + col0) =
            make_float2(tanh_fast(v0), tanh_fast(v1));
        *(float2*)(hs + (rowb + 8 + g) * 36 + col0) =
            make_float2(tanh_fast(v2), tanh_fast(v3));
    }
    __syncwarp();

    // ---------------- layer 2: 3 term accumulators ----------------
    float dhh[4][4], dhl[4][4], dlh[4][4];
#pragma unroll
    for (int nt = 0; nt < 4; nt++) {
        int col0 = nt * 8 + 2 * t4;
        dhh[nt][0] = b2s[col0];  dhh[nt][1] = b2s[col0 + 1];
        dhh[nt][2] = dhh[nt][0]; dhh[nt][3] = dhh[nt][1];
#pragma unroll
        for (int q = 0; q < 4; q++) { dhl[nt][q] = 0.f; dlh[nt][q] = 0.f; }
    }
    {
        const float* hr0 = hs + (rowb + g) * 36;
        const float* hr1 = hs + (rowb + 8 + g) * 36;
#pragma unroll
        for (int kt = 0; kt < 4; kt++) {
            int k0 = kt * 8 + t4;
            uint32 ah[4], al[4];
            split_tf32(hr0[k0],     ah[0], al[0]);
            split_tf32(hr1[k0],     ah[1], al[1]);
            split_tf32(hr0[k0 + 4], ah[2], al[2]);
            split_tf32(hr1[k0 + 4], ah[3], al[3]);
            int wk0 = (kt * 8 + t4) * 36;
            int wk1 = (kt * 8 + t4 + 4) * 36;
#pragma unroll
            for (int nt = 0; nt < 4; nt++) {
                int nc = nt * 8 + g;
                uint32 bh0 = w2hi[wk0 + nc], bh1 = w2hi[wk1 + nc];
                uint32 bl0 = w2lo[wk0 + nc], bl1 = w2lo[wk1 + nc];
                mma8(dhh[nt], ah[0], ah[1], ah[2], ah[3], bh0, bh1);
                mma8(dhl[nt], ah[0], ah[1], ah[2], ah[3], bl0, bl1);
                mma8(dlh[nt], al[0], al[1], al[2], al[3], bh0, bh1);
            }
        }
    }

    // ---- combine + store ----
    {
        int r0g = tile + rowb + g;
        int r1g = r0g + 8;
#pragma unroll
        for (int nt = 0; nt < 4; nt++) {
            int col0 = nt * 8 + 2 * t4;
            float v0 = dhh[nt][0] + (dhl[nt][0] + dlh[nt][0]);
            float v1 = dhh[nt][1] + (dhl[nt][1] + dlh[nt][1]);
            float v2 = dhh[nt][2] + (dhl[nt][2] + dlh[nt][2]);
            float v3 = dhh[nt][3] + (dhl[nt][3] + dlh[nt][3]);
            if (r0g < n)
                *(float2*)(out + (size_t)r0g * 32 + col0) = make_float2(v0, v1);
            if (r1g < n)
                *(float2*)(out + (size_t)r1g * 32 + col0) = make_float2(v2, v3);
        }
    }
}

// ---------------------------------------------------------------------------
// acc[i0[r]] += src[r]; acc[i1[r]] += src[r]   (row-wise float4 atomics)
__global__ void __launch_bounds__(256) scatter2_kernel(
    const float* __restrict__ src,
    const int* __restrict__ i0, const int* __restrict__ i1,
    float* __restrict__ acc, int n)
{
    int r = blockIdx.x * 256 + threadIdx.x;
    if (r >= n) return;
    const float4* s = (const float4*)(src + (size_t)r * 32);
    float4* d0 = (float4*)(acc + (size_t)i0[r] * 32);
    float4* d1 = (float4*)(acc + (size_t)i1[r] * 32);
#pragma unroll
    for (int q = 0; q < 8; q++) {
        float4 v = s[q];
        atomicAdd(d0 + q, v);
        atomicAdd(d1 + q, v);
    }
}

// acc[dstidx[r]] += src[srcidx[r]]
__global__ void __launch_bounds__(256) scatter1_kernel(
    const float* __restrict__ src,
    const int* __restrict__ srcidx, const int* __restrict__ dstidx,
    float* __restrict__ acc, int n)
{
    int r = blockIdx.x * 256 + threadIdx.x;
    if (r >= n) return;
    const float4* s = (const float4*)(src + (size_t)srcidx[r] * 32);
    float4* d = (float4*)(acc + (size_t)dstidx[r] * 32);
#pragma unroll
    for (int q = 0; q < 8; q++) atomicAdd(d + q, s[q]);
}

// ---------------------------------------------------------------------------
static inline int nblk256(int n)  { return (n + 255) / 256; }
static inline int nblk128t(int n) { return (n + 127) / 128; }

static inline int smem_bytes(int P)
{
    int K1 = P * 32;
    int floats = 128 * (K1 + 4)
               + 2 * K1 * 36
               + 2 * 32 * 36
               + 128 * 36
               + 64;
    return floats * 4;
}

extern "C" void kernel_launch(void* const* d_in, const int* in_sizes, int n_in,
                              void* d_out, int out_size)
{
    const float* h1     = (const float*)d_in[0];
    const float* h2     = (const float*)d_in[1];
    const float* h3     = (const float*)d_in[2];
    const float* h4     = (const float*)d_in[3];
    const float* upW1   = (const float*)d_in[4];
    const float* upb1   = (const float*)d_in[5];
    const float* upW2   = (const float*)d_in[6];
    const float* upb2   = (const float*)d_in[7];
    const float* dnW1   = (const float*)d_in[8];
    const float* dnb1   = (const float*)d_in[9];
    const float* dnW2   = (const float*)d_in[10];
    const float* dnb2   = (const float*)d_in[11];
    const float* rW1    = (const float*)d_in[12];
    const float* rb1    = (const float*)d_in[13];
    const float* rW2    = (const float*)d_in[14];
    const float* rb2    = (const float*)d_in[15];
    const int* idx2_0   = (const int*)d_in[16];
    const int* idx2_1   = (const int*)d_in[17];
    const int* idx3_0   = (const int*)d_in[18];
    const int* idx3_1   = (const int*)d_in[19];
    const int* idx4_0   = (const int*)d_in[20];
    const int* idx4_1   = (const int*)d_in[21];
    const int* ring_src = (const int*)d_in[22];
    const int* ring_dst = (const int*)d_in[23];

    const int N1 = in_sizes[0] / 32;
    const int N2 = in_sizes[1] / 32;
    const int N3 = in_sizes[2] / 32;
    const int N4 = in_sizes[3] / 32;
    const int ER = in_sizes[22];
    const int NR = out_size / 32 - (N1 + N2 + N3 + N4);

    float* out  = (float*)d_out;
    float* out1 = out;
    float* out2 = out1 + (size_t)N1 * 32;
    float* out3 = out2 + (size_t)N2 * 32;
    float* out4 = out3 + (size_t)N3 * 32;
    float* outR = out4 + (size_t)N4 * 32;

    float *h2buf, *h3buf, *acc3, *acc2, *acc1, *accr, *h1mid;
    cudaGetSymbolAddress((void**)&h2buf, g_h2);
    cudaGetSymbolAddress((void**)&h3buf, g_h3);
    cudaGetSymbolAddress((void**)&acc3,  g_acc3);
    cudaGetSymbolAddress((void**)&acc2,  g_acc2);
    cudaGetSymbolAddress((void**)&acc1,  g_acc1);
    cudaGetSymbolAddress((void**)&accr,  g_accr);
    cudaGetSymbolAddress((void**)&h1mid, g_h1mid);

    const int SM3 = smem_bytes(3);
    const int SM2 = smem_bytes(2);
    cudaFuncSetAttribute(mlp_mma_kernel<3, true>,
        cudaFuncAttributeMaxDynamicSharedMemorySize, SM3);
    cudaFuncSetAttribute(mlp_mma_kernel<2, false>,
        cudaFuncAttributeMaxDynamicSharedMemorySize, SM2);

    // ---- zero all accumulators once ----
    zero_multi_kernel<<<2048, 256>>>(
        (float4*)acc3, N3 * 8, (float4*)acc2, N2 * 8,
        (float4*)acc1, N1 * 8, (float4*)accr, N1 * 8,
        (float4*)outR, NR * 8);

    // ---- up pass ----
    mlp_mma_kernel<3, true><<<nblk128t(N2), 256, SM3>>>(h2, h1, idx2_0, idx2_1,
        upW1 + 0 * 96 * 32, upb1 + 0 * 32, upW2 + 0 * 1024, upb2 + 0 * 32,
        h2buf, N2);
    mlp_mma_kernel<3, true><<<nblk128t(N3), 256, SM3>>>(h3, h2buf, idx3_0, idx3_1,
        upW1 + 1 * 96 * 32, upb1 + 1 * 32, upW2 + 1 * 1024, upb2 + 1 * 32,
        h3buf, N3);
    mlp_mma_kernel<3, true><<<nblk128t(N4), 256, SM3>>>(h4, h3buf, idx4_0, idx4_1,
        upW1 + 2 * 96 * 32, upb1 + 2 * 32, upW2 + 2 * 1024, upb2 + 2 * 32,
        out4, N4);

    // ---- down pass ----
    scatter2_kernel<<<nblk256(N4), 256>>>(out4, idx4_0, idx4_1, acc3, N4);
    mlp_mma_kernel<2, false><<<nblk128t(N3), 256, SM2>>>(h3buf, acc3, 0, 0,
        dnW1 + 2 * 64 * 32, dnb1 + 2 * 32, dnW2 + 2 * 1024, dnb2 + 2 * 32,
        out3, N3);

    scatter2_kernel<<<nblk256(N3), 256>>>(out3, idx3_0, idx3_1, acc2, N3);
    mlp_mma_kernel<2, false><<<nblk128t(N2), 256, SM2>>>(h2buf, acc2, 0, 0,
        dnW1 + 1 * 64 * 32, dnb1 + 1 * 32, dnW2 + 1 * 1024, dnb2 + 1 * 32,
        out2, N2);

    scatter2_kernel<<<nblk256(N2), 256>>>(out2, idx2_0, idx2_1, acc1, N2);
    mlp_mma_kernel<2, false><<<nblk128t(N1), 256, SM2>>>(h1, acc1, 0, 0,
        dnW1 + 0 * 64 * 32, dnb1 + 0 * 32, dnW2 + 0 * 1024, dnb2 + 0 * 32,
        h1mid, N1);

    // ---- ring ----
    scatter1_kernel<<<nblk256(ER), 256>>>(h1mid, ring_src, ring_dst, outR, ER);
    scatter1_kernel<<<nblk256(ER), 256>>>(outR, ring_dst, ring_src, accr, ER);
    mlp_mma_kernel<2, false><<<nblk128t(N1), 256, SM2>>>(h1mid, accr, 0, 0,
        rW1, rb1, rW2, rb2, out1, N1);
}

// round 13
// speedup vs baseline: 1.5044x; 1.4739x over previous
#include <cuda_runtime.h>
#include <cstddef>
#include <cstdint>

// ---------------------------------------------------------------------------
// HMP hierarchical message passing — R13: bf16 2-split tensor-core MLPs.
//  * mma.sync m16n8k16 bf16, 3 terms (hh, hl, lh); missing ll ~2^-16 rel
//  * x and W pre-split into packed bf16 hi/lo pairs in SMEM (no cvt in loop)
//  * layer 2 A-fragments built in registers from layer-1 accumulators
//    (fragment-layout identity) -> no h SMEM round-trip
//  * 256-thr blocks, 8 warps, 1 m16-tile/warp, 128-row tile/block
// ---------------------------------------------------------------------------

typedef unsigned int uint32;

#define N1MAX 250000
#define N2MAX 500000
#define N3MAX 1000000

__device__ float g_h2   [(size_t)N2MAX * 32];
__device__ float g_h3   [(size_t)N3MAX * 32];
__device__ float g_acc3 [(size_t)N3MAX * 32];
__device__ float g_acc2 [(size_t)N2MAX * 32];
__device__ float g_acc1 [(size_t)N1MAX * 32];
__device__ float g_accr [(size_t)N1MAX * 32];
__device__ float g_h1mid[(size_t)N1MAX * 32];

// ---------------------------------------------------------------------------
__device__ __forceinline__ float tanh_fast(float x)
{
    float cx = fminf(fmaxf(x, -15.f), 15.f);
    float e  = __expf(2.f * cx);
    return __fdividef(e - 1.f, e + 1.f);
}

// split (v0,v1) into packed bf16 hi pair (truncated) + bf16 lo pair (residual).
// lower 16 bits of the u32 = v0's bf16 (even k), upper = v1's (odd k).
__device__ __forceinline__ void split2_bf16(float v0, float v1,
                                            uint32& hi, uint32& lo)
{
    uint32 u0 = __float_as_uint(v0), u1 = __float_as_uint(v1);
    hi = (u1 & 0xFFFF0000u) | (u0 >> 16);
    float l0 = v0 - __uint_as_float(u0 & 0xFFFF0000u);
    float l1 = v1 - __uint_as_float(u1 & 0xFFFF0000u);
    asm("cvt.rn.bf16x2.f32 %0, %1, %2;" : "=r"(lo) : "f"(l1), "f"(l0));
}

__device__ __forceinline__ void mma16(float c[4], const uint32 a[4],
                                      uint32 b0, uint32 b1)
{
    asm volatile(
        "mma.sync.aligned.m16n8k16.row.col.f32.bf16.bf16.f32 "
        "{%0,%1,%2,%3},{%4,%5,%6,%7},{%8,%9},{%0,%1,%2,%3};"
        : "+f"(c[0]), "+f"(c[1]), "+f"(c[2]), "+f"(c[3])
        : "r"(a[0]), "r"(a[1]), "r"(a[2]), "r"(a[3]), "r"(b0), "r"(b1));
}

// ---------------------------------------------------------------------------
__global__ void __launch_bounds__(256) zero_multi_kernel(
    float4* __restrict__ p0, int n0, float4* __restrict__ p1, int n1,
    float4* __restrict__ p2, int n2, float4* __restrict__ p3, int n3,
    float4* __restrict__ p4, int n4)
{
    const float4 z = make_float4(0.f, 0.f, 0.f, 0.f);
    int total = n0 + n1 + n2 + n3 + n4;
    for (int i = blockIdx.x * 256 + threadIdx.x; i < total; i += gridDim.x * 256) {
        int j = i;
        if (j < n0) { p0[j] = z; continue; } j -= n0;
        if (j < n1) { p1[j] = z; continue; } j -= n1;
        if (j < n2) { p2[j] = z; continue; } j -= n2;
        if (j < n3) { p3[j] = z; continue; } j -= n3;
        p4[j] = z;
    }
}

// ---------------------------------------------------------------------------
// bf16-split tensor-core MLP. 128-row tile, 8 warps, 16 rows/warp.
// x = [ self[r] | blocks from 'other' ], P blocks of 32 (P=2 or 3).
// out[r] = tanh(x@W1+b1)@W2+b2
template<int P, bool GATHER>
__global__ void __launch_bounds__(256) mlp_bf_kernel(
    const float* __restrict__ self, const float* __restrict__ other,
    const int* __restrict__ gi0, const int* __restrict__ gi1,
    const float* __restrict__ W1, const float* __restrict__ b1,
    const float* __restrict__ W2, const float* __restrict__ b2,
    float* __restrict__ out, int n)
{
    extern __shared__ uint32 smu[];
    const int KP  = P * 16;        // k-pairs in layer-1
    const int XSu = KP + 4;        // xs row stride (u32) — conflict-free
    uint32* xsh = smu;                        // [128][XSu]
    uint32* xsl = xsh + 128 * XSu;
    uint32* w1h = xsl + 128 * XSu;            // [KP][36]
    uint32* w1l = w1h + KP * 36;
    uint32* w2h = w1l + KP * 36;              // [16][36]
    uint32* w2l = w2h + 16 * 36;
    float*  b1s = (float*)(w2l + 16 * 36);    // [32]
    float*  b2s = b1s + 32;                   // [32]

    int tid  = threadIdx.x;
    int tile = blockIdx.x * 128;

    // ---- weights: load + bf16-split (pairs along k) ----
    for (int idx = tid; idx < KP * 32; idx += 256) {
        int p = idx >> 5, col = idx & 31;
        float v0 = W1[(2 * p) * 32 + col];
        float v1 = W1[(2 * p + 1) * 32 + col];
        uint32 hi, lo; split2_bf16(v0, v1, hi, lo);
        w1h[p * 36 + col] = hi; w1l[p * 36 + col] = lo;
    }
    for (int idx = tid; idx < 16 * 32; idx += 256) {
        int p = idx >> 5, col = idx & 31;
        float v0 = W2[(2 * p) * 32 + col];
        float v1 = W2[(2 * p + 1) * 32 + col];
        uint32 hi, lo; split2_bf16(v0, v1, hi, lo);
        w2h[p * 36 + col] = hi; w2l[p * 36 + col] = lo;
    }
    if (tid < 32) { b1s[tid] = b1[tid]; b2s[tid] = b2[tid]; }

    // ---- stage x tile: coalesced gather + bf16 split ----
    {
        int rl = tid >> 3;       // 0..31
        int c  = tid & 7;        // float4 index in 32-float block
        for (int pass = 0; pass < 4; pass++) {
            int row = rl + pass * 32;
            int r = min(tile + row, n - 1);
#pragma unroll
            for (int p = 0; p < P; p++) {
                const float* src;
                if (p == 0)      src = self + (size_t)r * 32;
                else if (GATHER) src = other + (size_t)((p == 1) ? gi0[r] : gi1[r]) * 32;
                else             src = other + (size_t)r * 32;
                float4 v = ((const float4*)src)[c];
                uint32 h0, l0, h1, l1;
                split2_bf16(v.x, v.y, h0, l0);
                split2_bf16(v.z, v.w, h1, l1);
                int base = row * XSu + p * 16 + 2 * c;
                xsh[base] = h0; xsh[base + 1] = h1;
                xsl[base] = l0; xsl[base + 1] = l1;
            }
        }
    }
    __syncthreads();

    int lane = tid & 31;
    int warp = tid >> 5;
    int g    = lane >> 2;
    int t4   = lane & 3;
    int rowb = warp * 16;

    // ---------------- layer 1 ----------------
    float chh[4][4], chl[4][4], clh[4][4];
#pragma unroll
    for (int nt = 0; nt < 4; nt++) {
        int col0 = nt * 8 + 2 * t4;
        chh[nt][0] = b1s[col0];  chh[nt][1] = b1s[col0 + 1];
        chh[nt][2] = chh[nt][0]; chh[nt][3] = chh[nt][1];
#pragma unroll
        for (int q = 0; q < 4; q++) { chl[nt][q] = 0.f; clh[nt][q] = 0.f; }
    }
    {
        const uint32* x0h = xsh + (rowb + g) * XSu;
        const uint32* x1h = xsh + (rowb + 8 + g) * XSu;
        const uint32* x0l = xsl + (rowb + g) * XSu;
        const uint32* x1l = xsl + (rowb + 8 + g) * XSu;
#pragma unroll
        for (int ks = 0; ks < 2 * P; ks++) {
            int pb = ks * 8;
            uint32 ah[4], al[4];
            ah[0] = x0h[pb + t4];     ah[1] = x1h[pb + t4];
            ah[2] = x0h[pb + t4 + 4]; ah[3] = x1h[pb + t4 + 4];
            al[0] = x0l[pb + t4];     al[1] = x1l[pb + t4];
            al[2] = x0l[pb + t4 + 4]; al[3] = x1l[pb + t4 + 4];
            int wk0 = (pb + t4) * 36;
            int wk1 = (pb + t4 + 4) * 36;
#pragma unroll
            for (int nt = 0; nt < 4; nt++) {
                int nc = nt * 8 + g;
                uint32 bh0 = w1h[wk0 + nc], bh1 = w1h[wk1 + nc];
                uint32 bl0 = w1l[wk0 + nc], bl1 = w1l[wk1 + nc];
                mma16(chh[nt], ah, bh0, bh1);
                mma16(chl[nt], ah, bl0, bl1);
                mma16(clh[nt], al, bh0, bh1);
            }
        }
    }

    // ---- combine + tanh + build layer-2 A fragments in registers ----
    // Fragment identity: c[nt][0],[1] = (row g, cols nt*8+2t4, +1) which is
    // exactly A-pair (ks = nt>>1, slot = nt&1) for the next m16n8k16.
    uint32 Ah[2][4], Al[2][4];
#pragma unroll
    for (int nt = 0; nt < 4; nt++) {
        float v0 = tanh_fast(chh[nt][0] + (chl[nt][0] + clh[nt][0]));
        float v1 = tanh_fast(chh[nt][1] + (chl[nt][1] + clh[nt][1]));
        float v2 = tanh_fast(chh[nt][2] + (chl[nt][2] + clh[nt][2]));
        float v3 = tanh_fast(chh[nt][3] + (chl[nt][3] + clh[nt][3]));
        int ks = nt >> 1, sl = (nt & 1) * 2;
        split2_bf16(v0, v1, Ah[ks][sl + 0], Al[ks][sl + 0]);   // row g
        split2_bf16(v2, v3, Ah[ks][sl + 1], Al[ks][sl + 1]);   // row g+8
    }
    // NOTE: a-register order is {a0=(g,k lo), a1=(g+8,k lo), a2=(g,k hi), a3=(g+8,k hi)}
    // sl mapping above yields exactly that: nt even -> slots 0,1; nt odd -> 2,3.

    // ---------------- layer 2 ----------------
    float dhh[4][4], dhl[4][4], dlh[4][4];
#pragma unroll
    for (int nt = 0; nt < 4; nt++) {
        int col0 = nt * 8 + 2 * t4;
        dhh[nt][0] = b2s[col0];  dhh[nt][1] = b2s[col0 + 1];
        dhh[nt][2] = dhh[nt][0]; dhh[nt][3] = dhh[nt][1];
#pragma unroll
        for (int q = 0; q < 4; q++) { dhl[nt][q] = 0.f; dlh[nt][q] = 0.f; }
    }
#pragma unroll
    for (int ks = 0; ks < 2; ks++) {
        int pb = ks * 8;
        int wk0 = (pb + t4) * 36;
        int wk1 = (pb + t4 + 4) * 36;
#pragma unroll
        for (int nt = 0; nt < 4; nt++) {
            int nc = nt * 8 + g;
            uint32 bh0 = w2h[wk0 + nc], bh1 = w2h[wk1 + nc];
            uint32 bl0 = w2l[wk0 + nc], bl1 = w2l[wk1 + nc];
            mma16(dhh[nt], Ah[ks], bh0, bh1);
            mma16(dhl[nt], Ah[ks], bl0, bl1);
            mma16(dlh[nt], Al[ks], bh0, bh1);
        }
    }

    // ---- combine + store ----
    {
        int r0g = tile + rowb + g;
        int r1g = r0g + 8;
#pragma unroll
        for (int nt = 0; nt < 4; nt++) {
            int col0 = nt * 8 + 2 * t4;
            float v0 = dhh[nt][0] + (dhl[nt][0] + dlh[nt][0]);
            float v1 = dhh[nt][1] + (dhl[nt][1] + dlh[nt][1]);
            float v2 = dhh[nt][2] + (dhl[nt][2] + dlh[nt][2]);
            float v3 = dhh[nt][3] + (dhl[nt][3] + dlh[nt][3]);
            if (r0g < n)
                *(float2*)(out + (size_t)r0g * 32 + col0) = make_float2(v0, v1);
            if (r1g < n)
                *(float2*)(out + (size_t)r1g * 32 + col0) = make_float2(v2, v3);
        }
    }
}

// ---------------------------------------------------------------------------
// acc[i0[r]] += src[r]; acc[i1[r]] += src[r]   (row-wise float4 atomics)
__global__ void __launch_bounds__(256) scatter2_kernel(
    const float* __restrict__ src,
    const int* __restrict__ i0, const int* __restrict__ i1,
    float* __restrict__ acc, int n)
{
    int r = blockIdx.x * 256 + threadIdx.x;
    if (r >= n) return;
    const float4* s = (const float4*)(src + (size_t)r * 32);
    float4* d0 = (float4*)(acc + (size_t)i0[r] * 32);
    float4* d1 = (float4*)(acc + (size_t)i1[r] * 32);
#pragma unroll
    for (int q = 0; q < 8; q++) {
        float4 v = s[q];
        atomicAdd(d0 + q, v);
        atomicAdd(d1 + q, v);
    }
}

// acc[dstidx[r]] += src[srcidx[r]]
__global__ void __launch_bounds__(256) scatter1_kernel(
    const float* __restrict__ src,
    const int* __restrict__ srcidx, const int* __restrict__ dstidx,
    float* __restrict__ acc, int n)
{
    int r = blockIdx.x * 256 + threadIdx.x;
    if (r >= n) return;
    const float4* s = (const float4*)(src + (size_t)srcidx[r] * 32);
    float4* d = (float4*)(acc + (size_t)dstidx[r] * 32);
#pragma unroll
    for (int q = 0; q < 8; q++) atomicAdd(d + q, s[q]);
}

// ---------------------------------------------------------------------------
static inline int nblk256(int n)  { return (n + 255) / 256; }
static inline int nblk128t(int n) { return (n + 127) / 128; }

static inline int smem_bytes(int P)
{
    int KP = P * 16, XSu = KP + 4;
    int u32s = 2 * 128 * XSu + 2 * KP * 36 + 2 * 16 * 36 + 64;
    return u32s * 4;
}

extern "C" void kernel_launch(void* const* d_in, const int* in_sizes, int n_in,
                              void* d_out, int out_size)
{
    const float* h1     = (const float*)d_in[0];
    const float* h2     = (const float*)d_in[1];
    const float* h3     = (const float*)d_in[2];
    const float* h4     = (const float*)d_in[3];
    const float* upW1   = (const float*)d_in[4];
    const float* upb1   = (const float*)d_in[5];
    const float* upW2   = (const float*)d_in[6];
    const float* upb2   = (const float*)d_in[7];
    const float* dnW1   = (const float*)d_in[8];
    const float* dnb1   = (const float*)d_in[9];
    const float* dnW2   = (const float*)d_in[10];
    const float* dnb2   = (const float*)d_in[11];
    const float* rW1    = (const float*)d_in[12];
    const float* rb1    = (const float*)d_in[13];
    const float* rW2    = (const float*)d_in[14];
    const float* rb2    = (const float*)d_in[15];
    const int* idx2_0   = (const int*)d_in[16];
    const int* idx2_1   = (const int*)d_in[17];
    const int* idx3_0   = (const int*)d_in[18];
    const int* idx3_1   = (const int*)d_in[19];
    const int* idx4_0   = (const int*)d_in[20];
    const int* idx4_1   = (const int*)d_in[21];
    const int* ring_src = (const int*)d_in[22];
    const int* ring_dst = (const int*)d_in[23];

    const int N1 = in_sizes[0] / 32;
    const int N2 = in_sizes[1] / 32;
    const int N3 = in_sizes[2] / 32;
    const int N4 = in_sizes[3] / 32;
    const int ER = in_sizes[22];
    const int NR = out_size / 32 - (N1 + N2 + N3 + N4);

    float* out  = (float*)d_out;
    float* out1 = out;
    float* out2 = out1 + (size_t)N1 * 32;
    float* out3 = out2 + (size_t)N2 * 32;
    float* out4 = out3 + (size_t)N3 * 32;
    float* outR = out4 + (size_t)N4 * 32;

    float *h2buf, *h3buf, *acc3, *acc2, *acc1, *accr, *h1mid;
    cudaGetSymbolAddress((void**)&h2buf, g_h2);
    cudaGetSymbolAddress((void**)&h3buf, g_h3);
    cudaGetSymbolAddress((void**)&acc3,  g_acc3);
    cudaGetSymbolAddress((void**)&acc2,  g_acc2);
    cudaGetSymbolAddress((void**)&acc1,  g_acc1);
    cudaGetSymbolAddress((void**)&accr,  g_accr);
    cudaGetSymbolAddress((void**)&h1mid, g_h1mid);

    const int SM3 = smem_bytes(3);
    const int SM2 = smem_bytes(2);
    cudaFuncSetAttribute(mlp_bf_kernel<3, true>,
        cudaFuncAttributeMaxDynamicSharedMemorySize, SM3);
    cudaFuncSetAttribute(mlp_bf_kernel<2, false>,
        cudaFuncAttributeMaxDynamicSharedMemorySize, SM2);

    // ---- zero all accumulators once ----
    zero_multi_kernel<<<2048, 256>>>(
        (float4*)acc3, N3 * 8, (float4*)acc2, N2 * 8,
        (float4*)acc1, N1 * 8, (float4*)accr, N1 * 8,
        (float4*)outR, NR * 8);

    // ---- up pass ----
    mlp_bf_kernel<3, true><<<nblk128t(N2), 256, SM3>>>(h2, h1, idx2_0, idx2_1,
        upW1 + 0 * 96 * 32, upb1 + 0 * 32, upW2 + 0 * 1024, upb2 + 0 * 32,
        h2buf, N2);
    mlp_bf_kernel<3, true><<<nblk128t(N3), 256, SM3>>>(h3, h2buf, idx3_0, idx3_1,
        upW1 + 1 * 96 * 32, upb1 + 1 * 32, upW2 + 1 * 1024, upb2 + 1 * 32,
        h3buf, N3);
    mlp_bf_kernel<3, true><<<nblk128t(N4), 256, SM3>>>(h4, h3buf, idx4_0, idx4_1,
        upW1 + 2 * 96 * 32, upb1 + 2 * 32, upW2 + 2 * 1024, upb2 + 2 * 32,
        out4, N4);

    // ---- down pass ----
    scatter2_kernel<<<nblk256(N4), 256>>>(out4, idx4_0, idx4_1, acc3, N4);
    mlp_bf_kernel<2, false><<<nblk128t(N3), 256, SM2>>>(h3buf, acc3, 0, 0,
        dnW1 + 2 * 64 * 32, dnb1 + 2 * 32, dnW2 + 2 * 1024, dnb2 + 2 * 32,
        out3, N3);

    scatter2_kernel<<<nblk256(N3), 256>>>(out3, idx3_0, idx3_1, acc2, N3);
    mlp_bf_kernel<2, false><<<nblk128t(N2), 256, SM2>>>(h2buf, acc2, 0, 0,
        dnW1 + 1 * 64 * 32, dnb1 + 1 * 32, dnW2 + 1 * 1024, dnb2 + 1 * 32,
        out2, N2);

    scatter2_kernel<<<nblk256(N2), 256>>>(out2, idx2_0, idx2_1, acc1, N2);
    mlp_bf_kernel<2, false><<<nblk128t(N1), 256, SM2>>>(h1, acc1, 0, 0,
        dnW1 + 0 * 64 * 32, dnb1 + 0 * 32, dnW2 + 0 * 1024, dnb2 + 0 * 32,
        h1mid, N1);

    // ---- ring ----
    scatter1_kernel<<<nblk256(ER), 256>>>(h1mid, ring_src, ring_dst, outR, ER);
    scatter1_kernel<<<nblk256(ER), 256>>>(outR, ring_dst, ring_src, accr, ER);
    mlp_bf_kernel<2, false><<<nblk128t(N1), 256, SM2>>>(h1mid, accr, 0, 0,
        rW1, rb1, rW2, rb2, out1, N1);
}